// round 15
// baseline (speedup 1.0000x reference)
#include <cuda_runtime.h>
#include <cuda_bf16.h>
#include <cstdint>

namespace {

constexpr int kS  = 2048;
constexpr int kD  = 64;
constexpr int kBH = 32;
constexpr int kNE = kBH * kS * kD;        // 4,194,304 elements per tensor

// split-bf16 scratch planes (static __device__ = allowed scratch)
__device__ __align__(16) __nv_bfloat16 g_qh[kNE];
__device__ __align__(16) __nv_bfloat16 g_ql[kNE];
__device__ __align__(16) __nv_bfloat16 g_kh[kNE];
__device__ __align__(16) __nv_bfloat16 g_kl[kNE];
__device__ __align__(16) __nv_bfloat16 g_vh[kNE];
__device__ __align__(16) __nv_bfloat16 g_vl[kNE];

// smem 40KB/CTA -> 5 CTAs/SM (200KB).
//   K hi/lo single buffer : 0 / 4096          (8KB)
//   V hi/lo double buffer : 8192 + b*8192     (16KB)
//   Q hi/lo persistent    : 24576 / 32768     (16KB, 64 rows x 128B each)
constexpr int OFF_KH = 0, OFF_KL = 4096;
__device__ __forceinline__ uint32_t vh_slot(uint32_t sb, int b) { return sb + 8192  + b * 8192; }
__device__ __forceinline__ uint32_t vl_slot(uint32_t sb, int b) { return sb + 12288 + b * 8192; }
constexpr int OFF_QH = 24576;
constexpr int OFF_QL = 32768;
constexpr int SM_TOTAL = 40960;

__device__ __forceinline__ uint32_t cvta_sm(const void* p) {
    uint32_t a;
    asm("{ .reg .u64 t; cvta.to.shared.u64 t, %1; cvt.u32.u64 %0, t; }" : "=r"(a) : "l"(p));
    return a;
}

#define CP_COMMIT() asm volatile("cp.async.commit_group;" ::: "memory")
#define CP_WAIT(N)  asm volatile("cp.async.wait_group %0;" :: "n"(N) : "memory")

__device__ __forceinline__ void cp16(uint32_t dst, const void* src) {
    asm volatile("cp.async.cg.shared.global [%0], [%1], 16;" :: "r"(dst), "l"(src) : "memory");
}

// async-copy a [32 x 128B] tile (256 uint4) into XOR-swizzled smem (128 threads)
__device__ __forceinline__ void fill32(uint32_t dst, const uint4* __restrict__ src, int tid) {
#pragma unroll
    for (int i = tid; i < 256; i += 128) {
        int r = i >> 3, c = i & 7;
        cp16(dst + r * 128 + ((c ^ (r & 7)) << 4), src + i);
    }
}
// async-copy a [64 x 128B] tile (512 uint4) — Q prologue
__device__ __forceinline__ void fill64(uint32_t dst, const uint4* __restrict__ src, int tid) {
#pragma unroll
    for (int i = tid; i < 512; i += 128) {
        int r = i >> 3, c = i & 7;
        cp16(dst + r * 128 + ((c ^ (r & 7)) << 4), src + i);
    }
}

__device__ __forceinline__ void ldsm4(uint32_t* r, uint32_t a) {
    asm volatile("ldmatrix.sync.aligned.m8n8.x4.shared.b16 {%0,%1,%2,%3}, [%4];"
                 : "=r"(r[0]), "=r"(r[1]), "=r"(r[2]), "=r"(r[3]) : "r"(a));
}
__device__ __forceinline__ void ldsm4t(uint32_t* r, uint32_t a) {
    asm volatile("ldmatrix.sync.aligned.m8n8.x4.trans.shared.b16 {%0,%1,%2,%3}, [%4];"
                 : "=r"(r[0]), "=r"(r[1]), "=r"(r[2]), "=r"(r[3]) : "r"(a));
}

__device__ __forceinline__ void mma16816(float* d, const uint32_t* a, uint32_t b0, uint32_t b1) {
    asm volatile(
        "mma.sync.aligned.m16n8k16.row.col.f32.bf16.bf16.f32 "
        "{%0,%1,%2,%3}, {%4,%5,%6,%7}, {%8,%9}, {%0,%1,%2,%3};"
        : "+f"(d[0]), "+f"(d[1]), "+f"(d[2]), "+f"(d[3])
        : "r"(a[0]), "r"(a[1]), "r"(a[2]), "r"(a[3]), "r"(b0), "r"(b1));
}

__device__ __forceinline__ uint32_t frag_addr(uint32_t tile, int row0, int c16, int lane) {
    int r = row0 + (lane & 15);
    int c = c16 + (lane >> 4);
    return tile + r * 128 + ((c ^ (r & 7)) << 4);
}

__device__ __forceinline__ void split2(float a, float b, uint32_t& hi, uint32_t& lo) {
    __nv_bfloat162 h = __floats2bfloat162_rn(a, b);
    __nv_bfloat162 l = __floats2bfloat162_rn(a - __bfloat162float(h.x),
                                             b - __bfloat162float(h.y));
    hi = *reinterpret_cast<uint32_t*>(&h);
    lo = *reinterpret_cast<uint32_t*>(&l);
}

// S[16] = Q(16 rows, from smem) x K^T(32 rows), 3-product split, product-major ILP.
__device__ __forceinline__ void qk3_32(float* S, uint32_t smQh, uint32_t smQl, int qrow0,
                                       uint32_t smKh, uint32_t smKl, int lane) {
#pragma unroll
    for (int i = 0; i < 16; i++) S[i] = 0.f;
#pragma unroll
    for (int kk = 0; kk < 4; kk++) {
        uint32_t qh[4], ql[4], kh0[4], kl0[4], kh1[4], kl1[4];
        ldsm4(qh,  frag_addr(smQh, qrow0, 2 * kk, lane));
        ldsm4(ql,  frag_addr(smQl, qrow0, 2 * kk, lane));
        ldsm4(kh0, frag_addr(smKh, 0,  2 * kk, lane));
        ldsm4(kl0, frag_addr(smKl, 0,  2 * kk, lane));
        ldsm4(kh1, frag_addr(smKh, 16, 2 * kk, lane));
        ldsm4(kl1, frag_addr(smKl, 16, 2 * kk, lane));
        mma16816(S + 0,  qh, kh0[0], kh0[2]);
        mma16816(S + 4,  qh, kh0[1], kh0[3]);
        mma16816(S + 8,  qh, kh1[0], kh1[2]);
        mma16816(S + 12, qh, kh1[1], kh1[3]);
        mma16816(S + 0,  qh, kl0[0], kl0[2]);
        mma16816(S + 4,  qh, kl0[1], kl0[3]);
        mma16816(S + 8,  qh, kl1[0], kl1[2]);
        mma16816(S + 12, qh, kl1[1], kl1[3]);
        mma16816(S + 0,  ql, kh0[0], kh0[2]);
        mma16816(S + 4,  ql, kh0[1], kh0[3]);
        mma16816(S + 8,  ql, kh1[0], kh1[2]);
        mma16816(S + 12, ql, kh1[1], kh1[3]);
    }
}

// O[32] += P(16x32, unnormalized) x V(32 k-rows x 64 d), 3-product split.
__device__ __forceinline__ void pv32(float* O, const float* S,
                                     uint32_t smVh, uint32_t smVl, int lane) {
#pragma unroll
    for (int kk = 0; kk < 2; kk++) {
        const float* p = S + kk * 8;
        uint32_t ah[4], al[4];
        split2(p[0], p[1], ah[0], al[0]);
        split2(p[2], p[3], ah[1], al[1]);
        split2(p[4], p[5], ah[2], al[2]);
        split2(p[6], p[7], ah[3], al[3]);
#pragma unroll
        for (int gp = 0; gp < 2; gp++) {
            uint32_t vh0[4], vl0[4], vh1[4], vl1[4];
            ldsm4t(vh0, frag_addr(smVh, kk * 16, 2 * (2 * gp),     lane));
            ldsm4t(vl0, frag_addr(smVl, kk * 16, 2 * (2 * gp),     lane));
            ldsm4t(vh1, frag_addr(smVh, kk * 16, 2 * (2 * gp + 1), lane));
            ldsm4t(vl1, frag_addr(smVl, kk * 16, 2 * (2 * gp + 1), lane));
            float* o0 = O + gp * 16;
            mma16816(o0 + 0,  ah, vh0[0], vh0[1]);
            mma16816(o0 + 4,  ah, vh0[2], vh0[3]);
            mma16816(o0 + 8,  ah, vh1[0], vh1[1]);
            mma16816(o0 + 12, ah, vh1[2], vh1[3]);
            mma16816(o0 + 0,  ah, vl0[0], vl0[1]);
            mma16816(o0 + 4,  ah, vl0[2], vl0[3]);
            mma16816(o0 + 8,  ah, vl1[0], vl1[1]);
            mma16816(o0 + 12, ah, vl1[2], vl1[3]);
            mma16816(o0 + 0,  al, vh0[0], vh0[1]);
            mma16816(o0 + 4,  al, vh0[2], vh0[3]);
            mma16816(o0 + 8,  al, vh1[0], vh1[1]);
            mma16816(o0 + 12, al, vh1[2], vh1[3]);
        }
    }
}

__global__ void split_kernel(const float4* __restrict__ Q, const float4* __restrict__ K,
                             const float4* __restrict__ V, int n4) {
    uint2* qh = reinterpret_cast<uint2*>(g_qh);
    uint2* ql = reinterpret_cast<uint2*>(g_ql);
    uint2* kh = reinterpret_cast<uint2*>(g_kh);
    uint2* kl = reinterpret_cast<uint2*>(g_kl);
    uint2* vh = reinterpret_cast<uint2*>(g_vh);
    uint2* vl = reinterpret_cast<uint2*>(g_vl);
    for (int i = blockIdx.x * blockDim.x + threadIdx.x; i < n4; i += gridDim.x * blockDim.x) {
        float4 q = Q[i];
        uint32_t h0, l0, h1, l1;
        split2(q.x * 0.125f, q.y * 0.125f, h0, l0);
        split2(q.z * 0.125f, q.w * 0.125f, h1, l1);
        qh[i] = make_uint2(h0, h1); ql[i] = make_uint2(l0, l1);
        float4 k = K[i];
        split2(k.x, k.y, h0, l0);
        split2(k.z, k.w, h1, l1);
        kh[i] = make_uint2(h0, h1); kl[i] = make_uint2(l0, l1);
        float4 v = V[i];
        split2(v.x, v.y, h0, l0);
        split2(v.z, v.w, h1, l1);
        vh[i] = make_uint2(h0, h1); vl[i] = make_uint2(l0, l1);
    }
}

// ===== fused: unnormalized W + O + row sums, then in-kernel W normalize =====
// CTA = 128 threads / 4 warps, ONE 64-row q-tile, heavy-first; 5 CTAs/SM target.
// K single-buffered (prefetch after post-QK sync), V double-buffered (prefetch at top).
__global__ void __launch_bounds__(128, 5)
attn_fused(float* __restrict__ Og, float* __restrict__ Wg) {
    extern __shared__ char smb[];
    const uint32_t sb = cvta_sm(smb);
    const int tid  = threadIdx.x;
    const int warp = tid >> 5;
    const int lane = tid & 31;
    const int bh   = blockIdx.y;
    const int qt   = 31 - (int)blockIdx.x;         // heavy tiles first
    const int ns   = 2 * qt + 2;                   // 32-row k-steps

    float* wbase = Wg + ((size_t)bh * kS + (size_t)qt * 64) * kS;

    // zero strictly-masked columns [ns*32, S) with evict-first stores
    {
        int c0 = ns * 32;
        if (c0 < kS) {
            int per_row = (kS - c0) >> 2;
            int total   = 64 * per_row;
            float4 z = make_float4(0.f, 0.f, 0.f, 0.f);
            for (int i = tid; i < total; i += 128) {
                int r = i / per_row, c = i - r * per_row;
                __stcs(reinterpret_cast<float4*>(wbase + (size_t)r * kS + c0) + c, z);
            }
        }
    }

    // plane base pointers for this bh (uint4 units)
    const uint4* khb = reinterpret_cast<const uint4*>(g_kh) + ((size_t)bh * kS) * kD / 8;
    const uint4* klb = reinterpret_cast<const uint4*>(g_kl) + ((size_t)bh * kS) * kD / 8;
    const uint4* vhb = reinterpret_cast<const uint4*>(g_vh) + ((size_t)bh * kS) * kD / 8;
    const uint4* vlb = reinterpret_cast<const uint4*>(g_vl) + ((size_t)bh * kS) * kD / 8;

    // ---- prologue: Q (persistent smem), K0, V0 ----
    const size_t qtb = ((size_t)bh * kS + (size_t)qt * 64) * kD / 8;
    fill64(sb + OFF_QH, reinterpret_cast<const uint4*>(g_qh) + qtb, tid);
    fill64(sb + OFF_QL, reinterpret_cast<const uint4*>(g_ql) + qtb, tid);
    fill32(sb + OFF_KH, khb, tid);
    fill32(sb + OFF_KL, klb, tid);
    fill32(vh_slot(sb, 0), vhb, tid);
    fill32(vl_slot(sb, 0), vlb, tid);
    CP_COMMIT();

    // running prefetch sources (step 1 data)
    const uint4* khp = khb + 256;
    const uint4* klp = klb + 256;
    const uint4* vhp = vhb + 256;
    const uint4* vlp = vlb + 256;

    const int R    = qt * 64 + warp * 16;      // warp's global row base
    const int rowg = R + (lane >> 2);          // lo row (hi = +8)
    const int colb = (lane & 3) * 2;
    const int qrow0 = warp * 16;

    float* wrow_lo = wbase + (size_t)(warp * 16 + (lane >> 2)) * kS + colb;
    float* wrow_hi = wrow_lo + (size_t)8 * kS;

    float O[32];
#pragma unroll
    for (int i = 0; i < 32; i++) O[i] = 0.f;
    float sum_lo = 0.f, sum_hi = 0.f;

#pragma unroll 1
    for (int s = 0; s < ns; s++) {
        CP_WAIT(0);            // K(s), V(s) resident
        __syncthreads();

        const bool pre = (s + 1 < ns);
        if (pre) {             // V(s+1) -> alternate V buffer (read finished in s-1)
            fill32(vh_slot(sb, (s + 1) & 1), vhp, tid);
            fill32(vl_slot(sb, (s + 1) & 1), vlp, tid);
            CP_COMMIT();
            vhp += 256; vlp += 256;
        }

        const int C     = s * 32;
        const bool skip = (C > R + 15);
        const bool edge = (C + 31 > R);

        float S[16];
        if (!skip)
            qk3_32(S, sb + OFF_QH, sb + OFF_QL, qrow0, sb + OFF_KH, sb + OFF_KL, lane);

        __syncthreads();       // all warps done reading K buffer
        if (pre) {             // K(s+1) -> single K buffer; covered by epilogue+PV
            fill32(sb + OFF_KH, khp, tid);
            fill32(sb + OFF_KL, klp, tid);
            CP_COMMIT();
            khp += 256; klp += 256;
        }

#pragma unroll
        for (int f = 0; f < 4; f++) {
            int c0 = C + f * 8 + colb;
            float e0, e1, e2, e3;
            if (skip) {
                e0 = e1 = e2 = e3 = 0.f;
            } else {
                e0 = __expf(S[4 * f + 0]);
                e1 = __expf(S[4 * f + 1]);
                e2 = __expf(S[4 * f + 2]);
                e3 = __expf(S[4 * f + 3]);
                if (edge) {
                    if (c0     > rowg)     e0 = 0.f;
                    if (c0 + 1 > rowg)     e1 = 0.f;
                    if (c0     > rowg + 8) e2 = 0.f;
                    if (c0 + 1 > rowg + 8) e3 = 0.f;
                }
            }
            sum_lo += e0 + e1;
            sum_hi += e2 + e3;
            __stcs(reinterpret_cast<float2*>(wrow_lo + f * 8), make_float2(e0, e1));
            __stcs(reinterpret_cast<float2*>(wrow_hi + f * 8), make_float2(e2, e3));
            if (!skip) {
                S[4 * f + 0] = e0; S[4 * f + 1] = e1;
                S[4 * f + 2] = e2; S[4 * f + 3] = e3;
            }
        }
        wrow_lo += 32;
        wrow_hi += 32;

        if (!skip)
            pv32(O, S, vh_slot(sb, s & 1), vl_slot(sb, s & 1), lane);
    }

    // reduce row sums across the quad lanes
    sum_lo += __shfl_xor_sync(0xffffffffu, sum_lo, 1);
    sum_lo += __shfl_xor_sync(0xffffffffu, sum_lo, 2);
    sum_hi += __shfl_xor_sync(0xffffffffu, sum_hi, 1);
    sum_hi += __shfl_xor_sync(0xffffffffu, sum_hi, 2);
    const float rl_lo = 1.0f / sum_lo;
    const float rl_hi = 1.0f / sum_hi;

    // scale O in-register and store
    {
        float* olo = Og + ((size_t)bh * kS + (size_t)qt * 64 + warp * 16 + (lane >> 2)) * kD;
        float* ohi = olo + (size_t)8 * kD;
#pragma unroll
        for (int f = 0; f < 8; f++) {
            int d0 = f * 8 + colb;
            *reinterpret_cast<float2*>(olo + d0) =
                make_float2(O[4 * f + 0] * rl_lo, O[4 * f + 1] * rl_lo);
            *reinterpret_cast<float2*>(ohi + d0) =
                make_float2(O[4 * f + 2] * rl_hi, O[4 * f + 3] * rl_hi);
        }
    }

    // ---- in-kernel normalize of this tile's W (overlaps other CTAs' compute) ----
    float* rlsm = reinterpret_cast<float*>(smb);   // K region, dead now
    __syncthreads();
    if ((lane & 3) == 0) {
        rlsm[warp * 16 + (lane >> 2)]     = rl_lo;
        rlsm[warp * 16 + (lane >> 2) + 8] = rl_hi;
    }
    __syncthreads();

    const int nchunk = (qt + 1) * 16;   // float4 chunks of causal cols per row
#pragma unroll 1
    for (int r = warp * 16; r < warp * 16 + 16; r++) {
        const float rl = rlsm[r];
        float4* row = reinterpret_cast<float4*>(wbase + (size_t)r * kS);
#pragma unroll 4
        for (int c = lane; c < nchunk; c += 32) {
            float4 v = __ldcs(row + c);
            v.x *= rl; v.y *= rl; v.z *= rl; v.w *= rl;
            __stcs(row + c, v);
        }
    }
}

} // namespace

extern "C" void kernel_launch(void* const* d_in, const int* in_sizes, int n_in,
                              void* d_out, int out_size) {
    const float* Q = (const float*)d_in[0];
    const float* K = (const float*)d_in[1];
    const float* V = (const float*)d_in[2];
    (void)in_sizes; (void)n_in; (void)out_size;   // d_in[3] = tril mask, applied analytically

    float* out = (float*)d_out;                   // [B,H,S,D]
    float* w   = out + (size_t)kBH * kS * kD;     // [B,H,S,S]

    static bool attr_set = false;
    if (!attr_set) {
        cudaFuncSetAttribute(attn_fused, cudaFuncAttributeMaxDynamicSharedMemorySize, SM_TOTAL);
        attr_set = true;
    }

    split_kernel<<<2048, 256>>>((const float4*)Q, (const float4*)K, (const float4*)V, kNE / 4);
    dim3 grid(32, kBH);                           // 1024 CTAs, heavy-first, 5/SM capacity
    attn_fused<<<grid, 128, SM_TOTAL>>>(out, w);
}

// round 16
// speedup vs baseline: 1.3264x; 1.3264x over previous
#include <cuda_runtime.h>
#include <cuda_bf16.h>
#include <cstdint>

namespace {

constexpr int kS  = 2048;
constexpr int kD  = 64;
constexpr int kBH = 32;
constexpr int kNE = kBH * kS * kD;        // 4,194,304 elements per tensor

// split-bf16 scratch planes (static __device__ = allowed scratch)
__device__ __align__(16) __nv_bfloat16 g_qh[kNE];
__device__ __align__(16) __nv_bfloat16 g_ql[kNE];
__device__ __align__(16) __nv_bfloat16 g_kh[kNE];
__device__ __align__(16) __nv_bfloat16 g_kl[kNE];
__device__ __align__(16) __nv_bfloat16 g_vh[kNE];
__device__ __align__(16) __nv_bfloat16 g_vl[kNE];

// smem (32KB/CTA -> 4 CTAs/SM): 8 x 4KB slots, 32-row tiles [32 x 128B].
// Q staging (2 x 8KB) transiently overlays the V region before each tile's loop.
__device__ __forceinline__ uint32_t kh_slot(uint32_t sb, int b) { return sb + b * 8192; }
__device__ __forceinline__ uint32_t kl_slot(uint32_t sb, int b) { return sb + b * 8192 + 4096; }
__device__ __forceinline__ uint32_t vh_slot(uint32_t sb, int b) { return sb + 16384 + b * 8192; }
__device__ __forceinline__ uint32_t vl_slot(uint32_t sb, int b) { return sb + 16384 + b * 8192 + 4096; }
constexpr int SM_QSTAGE_H = 16384;   // 8KB (overlays V buf0)
constexpr int SM_QSTAGE_L = 24576;   // 8KB (overlays V buf1)
constexpr int SM_TOTAL    = 32768;

__device__ __forceinline__ uint32_t cvta_sm(const void* p) {
    uint32_t a;
    asm("{ .reg .u64 t; cvta.to.shared.u64 t, %1; cvt.u32.u64 %0, t; }" : "=r"(a) : "l"(p));
    return a;
}

#define CP_COMMIT() asm volatile("cp.async.commit_group;" ::: "memory")
#define CP_WAIT(N)  asm volatile("cp.async.wait_group %0;" :: "n"(N) : "memory")

__device__ __forceinline__ void cp16(uint32_t dst, const void* src) {
    asm volatile("cp.async.cg.shared.global [%0], [%1], 16;" :: "r"(dst), "l"(src) : "memory");
}

// async-copy a [32 x 128B] tile (256 uint4) into XOR-swizzled smem (128 threads)
__device__ __forceinline__ void fill32(uint32_t dst, const uint4* __restrict__ src, int tid) {
#pragma unroll
    for (int i = tid; i < 256; i += 128) {
        int r = i >> 3, c = i & 7;
        cp16(dst + r * 128 + ((c ^ (r & 7)) << 4), src + i);
    }
}
// async-copy a [64 x 128B] tile (512 uint4)
__device__ __forceinline__ void fill64(uint32_t dst, const uint4* __restrict__ src, int tid) {
#pragma unroll
    for (int i = tid; i < 512; i += 128) {
        int r = i >> 3, c = i & 7;
        cp16(dst + r * 128 + ((c ^ (r & 7)) << 4), src + i);
    }
}

__device__ __forceinline__ void ldsm4(uint32_t* r, uint32_t a) {
    asm volatile("ldmatrix.sync.aligned.m8n8.x4.shared.b16 {%0,%1,%2,%3}, [%4];"
                 : "=r"(r[0]), "=r"(r[1]), "=r"(r[2]), "=r"(r[3]) : "r"(a));
}
__device__ __forceinline__ void ldsm4t(uint32_t* r, uint32_t a) {
    asm volatile("ldmatrix.sync.aligned.m8n8.x4.trans.shared.b16 {%0,%1,%2,%3}, [%4];"
                 : "=r"(r[0]), "=r"(r[1]), "=r"(r[2]), "=r"(r[3]) : "r"(a));
}

__device__ __forceinline__ void mma16816(float* d, const uint32_t* a, uint32_t b0, uint32_t b1) {
    asm volatile(
        "mma.sync.aligned.m16n8k16.row.col.f32.bf16.bf16.f32 "
        "{%0,%1,%2,%3}, {%4,%5,%6,%7}, {%8,%9}, {%0,%1,%2,%3};"
        : "+f"(d[0]), "+f"(d[1]), "+f"(d[2]), "+f"(d[3])
        : "r"(a[0]), "r"(a[1]), "r"(a[2]), "r"(a[3]), "r"(b0), "r"(b1));
}

__device__ __forceinline__ uint32_t frag_addr(uint32_t tile, int row0, int c16, int lane) {
    int r = row0 + (lane & 15);
    int c = c16 + (lane >> 4);
    return tile + r * 128 + ((c ^ (r & 7)) << 4);
}

__device__ __forceinline__ void split2(float a, float b, uint32_t& hi, uint32_t& lo) {
    __nv_bfloat162 h = __floats2bfloat162_rn(a, b);
    __nv_bfloat162 l = __floats2bfloat162_rn(a - __bfloat162float(h.x),
                                             b - __bfloat162float(h.y));
    hi = *reinterpret_cast<uint32_t*>(&h);
    lo = *reinterpret_cast<uint32_t*>(&l);
}

// S[16] = Q(16 rows, regs) x K^T(32 rows), 3-product split, product-major ILP order.
__device__ __forceinline__ void qk3_32(float* S, const uint32_t qh[4][4], const uint32_t ql[4][4],
                                       uint32_t smKh, uint32_t smKl, int lane) {
#pragma unroll
    for (int i = 0; i < 16; i++) S[i] = 0.f;
#pragma unroll
    for (int kk = 0; kk < 4; kk++) {
        uint32_t kh0[4], kl0[4], kh1[4], kl1[4];
        ldsm4(kh0, frag_addr(smKh, 0,  2 * kk, lane));
        ldsm4(kl0, frag_addr(smKl, 0,  2 * kk, lane));
        ldsm4(kh1, frag_addr(smKh, 16, 2 * kk, lane));
        ldsm4(kl1, frag_addr(smKl, 16, 2 * kk, lane));
        mma16816(S + 0,  qh[kk], kh0[0], kh0[2]);
        mma16816(S + 4,  qh[kk], kh0[1], kh0[3]);
        mma16816(S + 8,  qh[kk], kh1[0], kh1[2]);
        mma16816(S + 12, qh[kk], kh1[1], kh1[3]);
        mma16816(S + 0,  qh[kk], kl0[0], kl0[2]);
        mma16816(S + 4,  qh[kk], kl0[1], kl0[3]);
        mma16816(S + 8,  qh[kk], kl1[0], kl1[2]);
        mma16816(S + 12, qh[kk], kl1[1], kl1[3]);
        mma16816(S + 0,  ql[kk], kh0[0], kh0[2]);
        mma16816(S + 4,  ql[kk], kh0[1], kh0[3]);
        mma16816(S + 8,  ql[kk], kh1[0], kh1[2]);
        mma16816(S + 12, ql[kk], kh1[1], kh1[3]);
    }
}

// O[32] += P(16x32, unnormalized) x V(32 k-rows x 64 d), 3-product split.
__device__ __forceinline__ void pv32(float* O, const float* S,
                                     uint32_t smVh, uint32_t smVl, int lane) {
#pragma unroll
    for (int kk = 0; kk < 2; kk++) {
        const float* p = S + kk * 8;
        uint32_t ah[4], al[4];
        split2(p[0], p[1], ah[0], al[0]);
        split2(p[2], p[3], ah[1], al[1]);
        split2(p[4], p[5], ah[2], al[2]);
        split2(p[6], p[7], ah[3], al[3]);
#pragma unroll
        for (int gp = 0; gp < 2; gp++) {     // g2 pairs {0,1}, {2,3}
            uint32_t vh0[4], vl0[4], vh1[4], vl1[4];
            ldsm4t(vh0, frag_addr(smVh, kk * 16, 2 * (2 * gp),     lane));
            ldsm4t(vl0, frag_addr(smVl, kk * 16, 2 * (2 * gp),     lane));
            ldsm4t(vh1, frag_addr(smVh, kk * 16, 2 * (2 * gp + 1), lane));
            ldsm4t(vl1, frag_addr(smVl, kk * 16, 2 * (2 * gp + 1), lane));
            float* o0 = O + gp * 16;
            mma16816(o0 + 0,  ah, vh0[0], vh0[1]);
            mma16816(o0 + 4,  ah, vh0[2], vh0[3]);
            mma16816(o0 + 8,  ah, vh1[0], vh1[1]);
            mma16816(o0 + 12, ah, vh1[2], vh1[3]);
            mma16816(o0 + 0,  ah, vl0[0], vl0[1]);
            mma16816(o0 + 4,  ah, vl0[2], vl0[3]);
            mma16816(o0 + 8,  ah, vl1[0], vl1[1]);
            mma16816(o0 + 12, ah, vl1[2], vl1[3]);
            mma16816(o0 + 0,  al, vh0[0], vh0[1]);
            mma16816(o0 + 4,  al, vh0[2], vh0[3]);
            mma16816(o0 + 8,  al, vh1[0], vh1[1]);
            mma16816(o0 + 12, al, vh1[2], vh1[3]);
        }
    }
}

__global__ void split_kernel(const float4* __restrict__ Q, const float4* __restrict__ K,
                             const float4* __restrict__ V, int n4) {
    uint2* qh = reinterpret_cast<uint2*>(g_qh);
    uint2* ql = reinterpret_cast<uint2*>(g_ql);
    uint2* kh = reinterpret_cast<uint2*>(g_kh);
    uint2* kl = reinterpret_cast<uint2*>(g_kl);
    uint2* vh = reinterpret_cast<uint2*>(g_vh);
    uint2* vl = reinterpret_cast<uint2*>(g_vl);
    for (int i = blockIdx.x * blockDim.x + threadIdx.x; i < n4; i += gridDim.x * blockDim.x) {
        float4 q = Q[i];
        uint32_t h0, l0, h1, l1;
        split2(q.x * 0.125f, q.y * 0.125f, h0, l0);
        split2(q.z * 0.125f, q.w * 0.125f, h1, l1);
        qh[i] = make_uint2(h0, h1); ql[i] = make_uint2(l0, l1);
        float4 k = K[i];
        split2(k.x, k.y, h0, l0);
        split2(k.z, k.w, h1, l1);
        kh[i] = make_uint2(h0, h1); kl[i] = make_uint2(l0, l1);
        float4 v = V[i];
        split2(v.x, v.y, h0, l0);
        split2(v.z, v.w, h1, l1);
        vh[i] = make_uint2(h0, h1); vl[i] = make_uint2(l0, l1);
    }
}

// ===== fused: unnormalized W + O + row sums, then in-kernel W normalize =====
// CTA = 128 threads / 4 warps. Each CTA processes TWO 64-row q-tiles:
// tile (31 - bx) [heavy] then tile bx [light] -> uniform 66 k-steps per CTA,
// 512 CTAs total = one wave at 4 CTAs/SM.
__global__ void __launch_bounds__(128, 4)
attn_fused(float* __restrict__ Og, float* __restrict__ Wg) {
    extern __shared__ char smb[];
    const uint32_t sb = cvta_sm(smb);
    const int tid  = threadIdx.x;
    const int warp = tid >> 5;
    const int lane = tid & 31;
    const int bh   = blockIdx.y;

#pragma unroll 1
    for (int half = 0; half < 2; half++) {
        const int qt = half ? (int)blockIdx.x : 31 - (int)blockIdx.x;
        const int ns = 2 * qt + 2;                     // 32-row k-steps

        float* wbase = Wg + ((size_t)bh * kS + (size_t)qt * 64) * kS;

        __syncthreads();   // half boundary: prior tile fully done before refills

        // zero strictly-masked columns [ns*32, S) with evict-first stores
        {
            int c0 = ns * 32;
            if (c0 < kS) {
                int per_row = (kS - c0) >> 2;
                int total   = 64 * per_row;
                float4 z = make_float4(0.f, 0.f, 0.f, 0.f);
                for (int i = tid; i < total; i += 128) {
                    int r = i / per_row, c = i - r * per_row;
                    __stcs(reinterpret_cast<float4*>(wbase + (size_t)r * kS + c0) + c, z);
                }
            }
        }

        // ---- stage Q (hi/lo) + K step 0; pull Q frags to registers; then launch V0 ----
        const size_t qtb = ((size_t)bh * kS + (size_t)qt * 64) * kD / 8;   // uint4 index
        fill64(sb + SM_QSTAGE_H, reinterpret_cast<const uint4*>(g_qh) + qtb, tid);
        fill64(sb + SM_QSTAGE_L, reinterpret_cast<const uint4*>(g_ql) + qtb, tid);
        {
            size_t tb = ((size_t)bh * kS) * kD / 8;
            fill32(kh_slot(sb, 0), reinterpret_cast<const uint4*>(g_kh) + tb, tid);
            fill32(kl_slot(sb, 0), reinterpret_cast<const uint4*>(g_kl) + tb, tid);
        }
        CP_COMMIT();
        CP_WAIT(0);
        __syncthreads();

        uint32_t qhf[4][4], qlf[4][4];
#pragma unroll
        for (int kk = 0; kk < 4; kk++) {
            ldsm4(qhf[kk], frag_addr(sb + SM_QSTAGE_H, warp * 16, 2 * kk, lane));
            ldsm4(qlf[kk], frag_addr(sb + SM_QSTAGE_L, warp * 16, 2 * kk, lane));
        }
        __syncthreads();   // staging reads done before V0 overwrites the region
        {
            size_t tb = ((size_t)bh * kS) * kD / 8;
            fill32(vh_slot(sb, 0), reinterpret_cast<const uint4*>(g_vh) + tb, tid);
            fill32(vl_slot(sb, 0), reinterpret_cast<const uint4*>(g_vl) + tb, tid);
            CP_COMMIT();
        }

        const int R    = qt * 64 + warp * 16;      // warp's global row base
        const int rowg = R + (lane >> 2);          // lo row (hi = +8)
        const int colb = (lane & 3) * 2;

        float O[32];
#pragma unroll
        for (int i = 0; i < 32; i++) O[i] = 0.f;
        float sum_lo = 0.f, sum_hi = 0.f;

#pragma unroll 1
        for (int s = 0; s < ns; s++) {
            CP_WAIT(0);
            __syncthreads();
            if (s + 1 < ns) {   // prefetch next K and V into alternate buffers
                size_t tb = ((size_t)bh * kS + (size_t)(s + 1) * 32) * kD / 8;
                int b = (s + 1) & 1;
                fill32(kh_slot(sb, b), reinterpret_cast<const uint4*>(g_kh) + tb, tid);
                fill32(kl_slot(sb, b), reinterpret_cast<const uint4*>(g_kl) + tb, tid);
                fill32(vh_slot(sb, b), reinterpret_cast<const uint4*>(g_vh) + tb, tid);
                fill32(vl_slot(sb, b), reinterpret_cast<const uint4*>(g_vl) + tb, tid);
                CP_COMMIT();
            }
            const int C     = s * 32;
            const bool skip = (C > R + 15);
            const bool edge = (C + 31 > R);
            float* wlo = wbase + (size_t)(warp * 16 + (lane >> 2)) * kS + C;
            float* whi = wlo + (size_t)8 * kS;

            float S[16];
            if (!skip)
                qk3_32(S, qhf, qlf, kh_slot(sb, s & 1), kl_slot(sb, s & 1), lane);

#pragma unroll
            for (int f = 0; f < 4; f++) {
                int c0 = C + f * 8 + colb;
                float e0, e1, e2, e3;
                if (skip) {
                    e0 = e1 = e2 = e3 = 0.f;
                } else {
                    e0 = __expf(S[4 * f + 0]);
                    e1 = __expf(S[4 * f + 1]);
                    e2 = __expf(S[4 * f + 2]);
                    e3 = __expf(S[4 * f + 3]);
                    if (edge) {
                        if (c0     > rowg)     e0 = 0.f;
                        if (c0 + 1 > rowg)     e1 = 0.f;
                        if (c0     > rowg + 8) e2 = 0.f;
                        if (c0 + 1 > rowg + 8) e3 = 0.f;
                    }
                }
                sum_lo += e0 + e1;
                sum_hi += e2 + e3;
                // default-policy stores: keep lines in L2 for the normalize re-read
                *reinterpret_cast<float2*>(wlo + f * 8 + colb) = make_float2(e0, e1);
                *reinterpret_cast<float2*>(whi + f * 8 + colb) = make_float2(e2, e3);
                if (!skip) {
                    S[4 * f + 0] = e0; S[4 * f + 1] = e1;
                    S[4 * f + 2] = e2; S[4 * f + 3] = e3;
                }
            }

            if (!skip)
                pv32(O, S, vh_slot(sb, s & 1), vl_slot(sb, s & 1), lane);
        }

        // reduce row sums across the quad lanes
        sum_lo += __shfl_xor_sync(0xffffffffu, sum_lo, 1);
        sum_lo += __shfl_xor_sync(0xffffffffu, sum_lo, 2);
        sum_hi += __shfl_xor_sync(0xffffffffu, sum_hi, 1);
        sum_hi += __shfl_xor_sync(0xffffffffu, sum_hi, 2);
        const float rl_lo = 1.0f / sum_lo;
        const float rl_hi = 1.0f / sum_hi;

        // scale O in-register and store
        {
            float* olo = Og + ((size_t)bh * kS + (size_t)qt * 64 + warp * 16 + (lane >> 2)) * kD;
            float* ohi = olo + (size_t)8 * kD;
#pragma unroll
            for (int f = 0; f < 8; f++) {
                int d0 = f * 8 + colb;
                *reinterpret_cast<float2*>(olo + d0) =
                    make_float2(O[4 * f + 0] * rl_lo, O[4 * f + 1] * rl_lo);
                *reinterpret_cast<float2*>(ohi + d0) =
                    make_float2(O[4 * f + 2] * rl_hi, O[4 * f + 3] * rl_hi);
            }
        }

        // ---- per-warp normalize of this tile's W rows (no CTA barrier needed):
        // rl for the warp's 16 rows lives in its own quad lanes -> shfl broadcast.
        const int nchunk = (qt + 1) * 16;   // float4 chunks of causal cols per row
#pragma unroll 1
        for (int rr = 0; rr < 16; rr++) {
            const int srcl = 4 * (rr & 7);
            const float a  = __shfl_sync(0xffffffffu, rl_lo, srcl);
            const float b  = __shfl_sync(0xffffffffu, rl_hi, srcl);
            const float rl = (rr < 8) ? a : b;
            float4* row = reinterpret_cast<float4*>(wbase + (size_t)(warp * 16 + rr) * kS);
#pragma unroll 4
            for (int c = lane; c < nchunk; c += 32) {
                float4 v = __ldcs(row + c);
                v.x *= rl; v.y *= rl; v.z *= rl; v.w *= rl;
                __stcs(row + c, v);
            }
        }
    }
}

} // namespace

extern "C" void kernel_launch(void* const* d_in, const int* in_sizes, int n_in,
                              void* d_out, int out_size) {
    const float* Q = (const float*)d_in[0];
    const float* K = (const float*)d_in[1];
    const float* V = (const float*)d_in[2];
    (void)in_sizes; (void)n_in; (void)out_size;   // d_in[3] = tril mask, applied analytically

    float* out = (float*)d_out;                   // [B,H,S,D]
    float* w   = out + (size_t)kBH * kS * kD;     // [B,H,S,S]

    static bool attr_set = false;
    if (!attr_set) {
        cudaFuncSetAttribute(attn_fused, cudaFuncAttributeMaxDynamicSharedMemorySize, SM_TOTAL);
        attr_set = true;
    }

    split_kernel<<<2048, 256>>>((const float4*)Q, (const float4*)K, (const float4*)V, kNE / 4);
    dim3 grid(16, kBH);                           // 512 paired CTAs = one uniform wave
    attn_fused<<<grid, 128, SM_TOTAL>>>(out, w);
}

// round 17
// speedup vs baseline: 1.3865x; 1.0453x over previous
#include <cuda_runtime.h>
#include <cuda_bf16.h>
#include <cstdint>

namespace {

constexpr int kS  = 2048;
constexpr int kD  = 64;
constexpr int kBH = 32;
constexpr int kNE = kBH * kS * kD;        // 4,194,304 elements per tensor
constexpr int kNT = 1024;                 // 32 qt x 32 bh tiles

// split-bf16 scratch planes (static __device__ = allowed scratch)
__device__ __align__(16) __nv_bfloat16 g_qh[kNE];
__device__ __align__(16) __nv_bfloat16 g_ql[kNE];
__device__ __align__(16) __nv_bfloat16 g_kh[kNE];
__device__ __align__(16) __nv_bfloat16 g_kl[kNE];
__device__ __align__(16) __nv_bfloat16 g_vh[kNE];
__device__ __align__(16) __nv_bfloat16 g_vl[kNE];
__device__ unsigned int g_tile_ctr;       // persistent-CTA work queue head

// smem (32KB tiles + 128B ctrl -> 4 CTAs/SM): 8 x 4KB slots, 32-row tiles [32 x 128B].
// Q staging (2 x 8KB) transiently overlays the V region before each tile's loop.
__device__ __forceinline__ uint32_t kh_slot(uint32_t sb, int b) { return sb + b * 8192; }
__device__ __forceinline__ uint32_t kl_slot(uint32_t sb, int b) { return sb + b * 8192 + 4096; }
__device__ __forceinline__ uint32_t vh_slot(uint32_t sb, int b) { return sb + 16384 + b * 8192; }
__device__ __forceinline__ uint32_t vl_slot(uint32_t sb, int b) { return sb + 16384 + b * 8192 + 4096; }
constexpr int SM_QSTAGE_H = 16384;   // 8KB (overlays V buf0)
constexpr int SM_QSTAGE_L = 24576;   // 8KB (overlays V buf1)
constexpr int SM_CTRL     = 32768;   // 4B tile-index broadcast
constexpr int SM_TOTAL    = 32896;

__device__ __forceinline__ uint32_t cvta_sm(const void* p) {
    uint32_t a;
    asm("{ .reg .u64 t; cvta.to.shared.u64 t, %1; cvt.u32.u64 %0, t; }" : "=r"(a) : "l"(p));
    return a;
}

#define CP_COMMIT() asm volatile("cp.async.commit_group;" ::: "memory")
#define CP_WAIT(N)  asm volatile("cp.async.wait_group %0;" :: "n"(N) : "memory")

__device__ __forceinline__ void cp16(uint32_t dst, const void* src) {
    asm volatile("cp.async.cg.shared.global [%0], [%1], 16;" :: "r"(dst), "l"(src) : "memory");
}

// async-copy a [32 x 128B] tile (256 uint4) into XOR-swizzled smem (128 threads)
__device__ __forceinline__ void fill32(uint32_t dst, const uint4* __restrict__ src, int tid) {
#pragma unroll
    for (int i = tid; i < 256; i += 128) {
        int r = i >> 3, c = i & 7;
        cp16(dst + r * 128 + ((c ^ (r & 7)) << 4), src + i);
    }
}
// async-copy a [64 x 128B] tile (512 uint4)
__device__ __forceinline__ void fill64(uint32_t dst, const uint4* __restrict__ src, int tid) {
#pragma unroll
    for (int i = tid; i < 512; i += 128) {
        int r = i >> 3, c = i & 7;
        cp16(dst + r * 128 + ((c ^ (r & 7)) << 4), src + i);
    }
}

__device__ __forceinline__ void ldsm4(uint32_t* r, uint32_t a) {
    asm volatile("ldmatrix.sync.aligned.m8n8.x4.shared.b16 {%0,%1,%2,%3}, [%4];"
                 : "=r"(r[0]), "=r"(r[1]), "=r"(r[2]), "=r"(r[3]) : "r"(a));
}
__device__ __forceinline__ void ldsm4t(uint32_t* r, uint32_t a) {
    asm volatile("ldmatrix.sync.aligned.m8n8.x4.trans.shared.b16 {%0,%1,%2,%3}, [%4];"
                 : "=r"(r[0]), "=r"(r[1]), "=r"(r[2]), "=r"(r[3]) : "r"(a));
}

__device__ __forceinline__ void mma16816(float* d, const uint32_t* a, uint32_t b0, uint32_t b1) {
    asm volatile(
        "mma.sync.aligned.m16n8k16.row.col.f32.bf16.bf16.f32 "
        "{%0,%1,%2,%3}, {%4,%5,%6,%7}, {%8,%9}, {%0,%1,%2,%3};"
        : "+f"(d[0]), "+f"(d[1]), "+f"(d[2]), "+f"(d[3])
        : "r"(a[0]), "r"(a[1]), "r"(a[2]), "r"(a[3]), "r"(b0), "r"(b1));
}

__device__ __forceinline__ uint32_t frag_addr(uint32_t tile, int row0, int c16, int lane) {
    int r = row0 + (lane & 15);
    int c = c16 + (lane >> 4);
    return tile + r * 128 + ((c ^ (r & 7)) << 4);
}

__device__ __forceinline__ void split2(float a, float b, uint32_t& hi, uint32_t& lo) {
    __nv_bfloat162 h = __floats2bfloat162_rn(a, b);
    __nv_bfloat162 l = __floats2bfloat162_rn(a - __bfloat162float(h.x),
                                             b - __bfloat162float(h.y));
    hi = *reinterpret_cast<uint32_t*>(&h);
    lo = *reinterpret_cast<uint32_t*>(&l);
}

// S[16] = Q(16 rows, regs) x K^T(32 rows), 3-product split, product-major ILP order.
__device__ __forceinline__ void qk3_32(float* S, const uint32_t qh[4][4], const uint32_t ql[4][4],
                                       uint32_t smKh, uint32_t smKl, int lane) {
#pragma unroll
    for (int i = 0; i < 16; i++) S[i] = 0.f;
#pragma unroll
    for (int kk = 0; kk < 4; kk++) {
        uint32_t kh0[4], kl0[4], kh1[4], kl1[4];
        ldsm4(kh0, frag_addr(smKh, 0,  2 * kk, lane));
        ldsm4(kl0, frag_addr(smKl, 0,  2 * kk, lane));
        ldsm4(kh1, frag_addr(smKh, 16, 2 * kk, lane));
        ldsm4(kl1, frag_addr(smKl, 16, 2 * kk, lane));
        mma16816(S + 0,  qh[kk], kh0[0], kh0[2]);
        mma16816(S + 4,  qh[kk], kh0[1], kh0[3]);
        mma16816(S + 8,  qh[kk], kh1[0], kh1[2]);
        mma16816(S + 12, qh[kk], kh1[1], kh1[3]);
        mma16816(S + 0,  qh[kk], kl0[0], kl0[2]);
        mma16816(S + 4,  qh[kk], kl0[1], kl0[3]);
        mma16816(S + 8,  qh[kk], kl1[0], kl1[2]);
        mma16816(S + 12, qh[kk], kl1[1], kl1[3]);
        mma16816(S + 0,  ql[kk], kh0[0], kh0[2]);
        mma16816(S + 4,  ql[kk], kh0[1], kh0[3]);
        mma16816(S + 8,  ql[kk], kh1[0], kh1[2]);
        mma16816(S + 12, ql[kk], kh1[1], kh1[3]);
    }
}

// O[32] += P(16x32, unnormalized) x V(32 k-rows x 64 d), 3-product split.
__device__ __forceinline__ void pv32(float* O, const float* S,
                                     uint32_t smVh, uint32_t smVl, int lane) {
#pragma unroll
    for (int kk = 0; kk < 2; kk++) {
        const float* p = S + kk * 8;
        uint32_t ah[4], al[4];
        split2(p[0], p[1], ah[0], al[0]);
        split2(p[2], p[3], ah[1], al[1]);
        split2(p[4], p[5], ah[2], al[2]);
        split2(p[6], p[7], ah[3], al[3]);
#pragma unroll
        for (int gp = 0; gp < 2; gp++) {     // g2 pairs {0,1}, {2,3}
            uint32_t vh0[4], vl0[4], vh1[4], vl1[4];
            ldsm4t(vh0, frag_addr(smVh, kk * 16, 2 * (2 * gp),     lane));
            ldsm4t(vl0, frag_addr(smVl, kk * 16, 2 * (2 * gp),     lane));
            ldsm4t(vh1, frag_addr(smVh, kk * 16, 2 * (2 * gp + 1), lane));
            ldsm4t(vl1, frag_addr(smVl, kk * 16, 2 * (2 * gp + 1), lane));
            float* o0 = O + gp * 16;
            mma16816(o0 + 0,  ah, vh0[0], vh0[1]);
            mma16816(o0 + 4,  ah, vh0[2], vh0[3]);
            mma16816(o0 + 8,  ah, vh1[0], vh1[1]);
            mma16816(o0 + 12, ah, vh1[2], vh1[3]);
            mma16816(o0 + 0,  ah, vl0[0], vl0[1]);
            mma16816(o0 + 4,  ah, vl0[2], vl0[3]);
            mma16816(o0 + 8,  ah, vl1[0], vl1[1]);
            mma16816(o0 + 12, ah, vl1[2], vl1[3]);
            mma16816(o0 + 0,  al, vh0[0], vh0[1]);
            mma16816(o0 + 4,  al, vh0[2], vh0[3]);
            mma16816(o0 + 8,  al, vh1[0], vh1[1]);
            mma16816(o0 + 12, al, vh1[2], vh1[3]);
        }
    }
}

__global__ void split_kernel(const float4* __restrict__ Q, const float4* __restrict__ K,
                             const float4* __restrict__ V, int n4) {
    if (blockIdx.x == 0 && threadIdx.x == 0) g_tile_ctr = 0;   // reset work queue each launch
    uint2* qh = reinterpret_cast<uint2*>(g_qh);
    uint2* ql = reinterpret_cast<uint2*>(g_ql);
    uint2* kh = reinterpret_cast<uint2*>(g_kh);
    uint2* kl = reinterpret_cast<uint2*>(g_kl);
    uint2* vh = reinterpret_cast<uint2*>(g_vh);
    uint2* vl = reinterpret_cast<uint2*>(g_vl);
    for (int i = blockIdx.x * blockDim.x + threadIdx.x; i < n4; i += gridDim.x * blockDim.x) {
        float4 q = Q[i];
        uint32_t h0, l0, h1, l1;
        split2(q.x * 0.125f, q.y * 0.125f, h0, l0);
        split2(q.z * 0.125f, q.w * 0.125f, h1, l1);
        qh[i] = make_uint2(h0, h1); ql[i] = make_uint2(l0, l1);
        float4 k = K[i];
        split2(k.x, k.y, h0, l0);
        split2(k.z, k.w, h1, l1);
        kh[i] = make_uint2(h0, h1); kl[i] = make_uint2(l0, l1);
        float4 v = V[i];
        split2(v.x, v.y, h0, l0);
        split2(v.z, v.w, h1, l1);
        vh[i] = make_uint2(h0, h1); vl[i] = make_uint2(l0, l1);
    }
}

// ===== fused: unnormalized W + O + row sums, then in-kernel W normalize =====
// Persistent CTAs (592 = 148 SMs x 4), each pulling 64-row q-tiles from a global
// atomic queue ordered heavy -> light. Tile body identical to the static version.
__global__ void __launch_bounds__(128, 4)
attn_fused(float* __restrict__ Og, float* __restrict__ Wg) {
    extern __shared__ char smb[];
    const uint32_t sb = cvta_sm(smb);
    const int tid  = threadIdx.x;
    const int warp = tid >> 5;
    const int lane = tid & 31;
    unsigned int* tshare = reinterpret_cast<unsigned int*>(smb + SM_CTRL);

    for (;;) {
        if (tid == 0) *tshare = atomicAdd(&g_tile_ctr, 1u);
        __syncthreads();               // broadcasts tile idx; also tile-boundary barrier
        const unsigned int t = *tshare;
        if (t >= (unsigned int)kNT) break;

        const int qt = 31 - (int)(t >> 5);   // heavy tiles first
        const int bh = (int)(t & 31u);
        const int ns = 2 * qt + 2;           // 32-row k-steps

        float* wbase = Wg + ((size_t)bh * kS + (size_t)qt * 64) * kS;

        // zero strictly-masked columns [ns*32, S) with evict-first stores
        {
            int c0 = ns * 32;
            if (c0 < kS) {
                int per_row = (kS - c0) >> 2;
                int total   = 64 * per_row;
                float4 z = make_float4(0.f, 0.f, 0.f, 0.f);
                for (int i = tid; i < total; i += 128) {
                    int r = i / per_row, c = i - r * per_row;
                    __stcs(reinterpret_cast<float4*>(wbase + (size_t)r * kS + c0) + c, z);
                }
            }
        }

        // ---- stage Q (hi/lo) + K step 0; pull Q frags to registers; then launch V0 ----
        const size_t qtb = ((size_t)bh * kS + (size_t)qt * 64) * kD / 8;   // uint4 index
        fill64(sb + SM_QSTAGE_H, reinterpret_cast<const uint4*>(g_qh) + qtb, tid);
        fill64(sb + SM_QSTAGE_L, reinterpret_cast<const uint4*>(g_ql) + qtb, tid);
        {
            size_t tb = ((size_t)bh * kS) * kD / 8;
            fill32(kh_slot(sb, 0), reinterpret_cast<const uint4*>(g_kh) + tb, tid);
            fill32(kl_slot(sb, 0), reinterpret_cast<const uint4*>(g_kl) + tb, tid);
        }
        CP_COMMIT();
        CP_WAIT(0);
        __syncthreads();

        uint32_t qhf[4][4], qlf[4][4];
#pragma unroll
        for (int kk = 0; kk < 4; kk++) {
            ldsm4(qhf[kk], frag_addr(sb + SM_QSTAGE_H, warp * 16, 2 * kk, lane));
            ldsm4(qlf[kk], frag_addr(sb + SM_QSTAGE_L, warp * 16, 2 * kk, lane));
        }
        __syncthreads();   // staging reads done before V0 overwrites the region
        {
            size_t tb = ((size_t)bh * kS) * kD / 8;
            fill32(vh_slot(sb, 0), reinterpret_cast<const uint4*>(g_vh) + tb, tid);
            fill32(vl_slot(sb, 0), reinterpret_cast<const uint4*>(g_vl) + tb, tid);
            CP_COMMIT();
        }

        const int R    = qt * 64 + warp * 16;      // warp's global row base
        const int rowg = R + (lane >> 2);          // lo row (hi = +8)
        const int colb = (lane & 3) * 2;

        float O[32];
#pragma unroll
        for (int i = 0; i < 32; i++) O[i] = 0.f;
        float sum_lo = 0.f, sum_hi = 0.f;

#pragma unroll 1
        for (int s = 0; s < ns; s++) {
            CP_WAIT(0);
            __syncthreads();
            if (s + 1 < ns) {   // prefetch next K and V into alternate buffers
                size_t tb = ((size_t)bh * kS + (size_t)(s + 1) * 32) * kD / 8;
                int b = (s + 1) & 1;
                fill32(kh_slot(sb, b), reinterpret_cast<const uint4*>(g_kh) + tb, tid);
                fill32(kl_slot(sb, b), reinterpret_cast<const uint4*>(g_kl) + tb, tid);
                fill32(vh_slot(sb, b), reinterpret_cast<const uint4*>(g_vh) + tb, tid);
                fill32(vl_slot(sb, b), reinterpret_cast<const uint4*>(g_vl) + tb, tid);
                CP_COMMIT();
            }
            const int C     = s * 32;
            const bool skip = (C > R + 15);
            const bool edge = (C + 31 > R);
            float* wlo = wbase + (size_t)(warp * 16 + (lane >> 2)) * kS + C;
            float* whi = wlo + (size_t)8 * kS;

            float S[16];
            if (!skip)
                qk3_32(S, qhf, qlf, kh_slot(sb, s & 1), kl_slot(sb, s & 1), lane);

#pragma unroll
            for (int f = 0; f < 4; f++) {
                int c0 = C + f * 8 + colb;
                float e0, e1, e2, e3;
                if (skip) {
                    e0 = e1 = e2 = e3 = 0.f;
                } else {
                    e0 = __expf(S[4 * f + 0]);
                    e1 = __expf(S[4 * f + 1]);
                    e2 = __expf(S[4 * f + 2]);
                    e3 = __expf(S[4 * f + 3]);
                    if (edge) {
                        if (c0     > rowg)     e0 = 0.f;
                        if (c0 + 1 > rowg)     e1 = 0.f;
                        if (c0     > rowg + 8) e2 = 0.f;
                        if (c0 + 1 > rowg + 8) e3 = 0.f;
                    }
                }
                sum_lo += e0 + e1;
                sum_hi += e2 + e3;
                // default-policy stores: keep lines in L2 for the normalize re-read
                *reinterpret_cast<float2*>(wlo + f * 8 + colb) = make_float2(e0, e1);
                *reinterpret_cast<float2*>(whi + f * 8 + colb) = make_float2(e2, e3);
                if (!skip) {
                    S[4 * f + 0] = e0; S[4 * f + 1] = e1;
                    S[4 * f + 2] = e2; S[4 * f + 3] = e3;
                }
            }

            if (!skip)
                pv32(O, S, vh_slot(sb, s & 1), vl_slot(sb, s & 1), lane);
        }

        // reduce row sums across the quad lanes
        sum_lo += __shfl_xor_sync(0xffffffffu, sum_lo, 1);
        sum_lo += __shfl_xor_sync(0xffffffffu, sum_lo, 2);
        sum_hi += __shfl_xor_sync(0xffffffffu, sum_hi, 1);
        sum_hi += __shfl_xor_sync(0xffffffffu, sum_hi, 2);
        const float rl_lo = 1.0f / sum_lo;
        const float rl_hi = 1.0f / sum_hi;

        // scale O in-register and store
        {
            float* olo = Og + ((size_t)bh * kS + (size_t)qt * 64 + warp * 16 + (lane >> 2)) * kD;
            float* ohi = olo + (size_t)8 * kD;
#pragma unroll
            for (int f = 0; f < 8; f++) {
                int d0 = f * 8 + colb;
                *reinterpret_cast<float2*>(olo + d0) =
                    make_float2(O[4 * f + 0] * rl_lo, O[4 * f + 1] * rl_lo);
                *reinterpret_cast<float2*>(ohi + d0) =
                    make_float2(O[4 * f + 2] * rl_hi, O[4 * f + 3] * rl_hi);
            }
        }

        // ---- per-warp normalize of this tile's W rows (no CTA barrier needed):
        // rl for the warp's 16 rows lives in its own quad lanes -> shfl broadcast.
        const int nchunk = (qt + 1) * 16;   // float4 chunks of causal cols per row
#pragma unroll 1
        for (int rr = 0; rr < 16; rr++) {
            const int srcl = 4 * (rr & 7);
            const float a  = __shfl_sync(0xffffffffu, rl_lo, srcl);
            const float b  = __shfl_sync(0xffffffffu, rl_hi, srcl);
            const float rl = (rr < 8) ? a : b;
            float4* row = reinterpret_cast<float4*>(wbase + (size_t)(warp * 16 + rr) * kS);
#pragma unroll 4
            for (int c = lane; c < nchunk; c += 32) {
                float4 v = __ldcs(row + c);
                v.x *= rl; v.y *= rl; v.z *= rl; v.w *= rl;
                __stcs(row + c, v);
            }
        }
    }
}

} // namespace

extern "C" void kernel_launch(void* const* d_in, const int* in_sizes, int n_in,
                              void* d_out, int out_size) {
    const float* Q = (const float*)d_in[0];
    const float* K = (const float*)d_in[1];
    const float* V = (const float*)d_in[2];
    (void)in_sizes; (void)n_in; (void)out_size;   // d_in[3] = tril mask, applied analytically

    float* out = (float*)d_out;                   // [B,H,S,D]
    float* w   = out + (size_t)kBH * kS * kD;     // [B,H,S,S]

    static bool attr_set = false;
    if (!attr_set) {
        cudaFuncSetAttribute(attn_fused, cudaFuncAttributeMaxDynamicSharedMemorySize, SM_TOTAL);
        attr_set = true;
    }

    split_kernel<<<2048, 256>>>((const float4*)Q, (const float4*)K, (const float4*)V, kNE / 4);
    attn_fused<<<592, 128, SM_TOTAL>>>(out, w);   // persistent CTAs, 4/SM x 148 SMs
}